// round 15
// baseline (speedup 1.0000x reference)
#include <cuda_runtime.h>
#include <cuda_fp16.h>
#include <math.h>
#include <stdint.h>

#define BB 8
#define C1D 256
#define C2D 128
#define C3D 512
#define NS 32
#define TT 256
#define DD 64
#define NVALID 2080   // number of (h,w) with h<=w, h,w in [0,64)

// ---------------- device scratch ----------------
__device__ __align__(16) __half g_xh[BB*TT*C2D];          // conv out [b][t][c] 0.5 MB
__device__ __align__(16) __half g_w3p[NS*C3D*C2D];        // w3 [k][o][c] fp16   4 MB
__device__ __align__(16) __half g_z[(size_t)NS*BB*TT*C3D];// z  [k][b][t][o]    67 MB
__device__ float  g_x3[(size_t)BB*NVALID*C3D];            // x3 [b][j][o]       34 MB
__device__ int    g_to[NVALID*192];                       // flat fused z offsets (b=0)
__device__ float  g_wl[NVALID*192];                       // flat tap weights
__device__ int    g_tot[NVALID];                          // taps per j
__device__ int    g_vp[NVALID];
__device__ float  g_cst[C2D];

// ---------------- helpers ----------------
__device__ __forceinline__ uint32_t smem_u32(const void* p) {
    uint32_t a;
    asm("{ .reg .u64 t; cvta.to.shared.u64 t, %1; cvt.u32.u64 %0, t; }" : "=r"(a) : "l"(p));
    return a;
}
__device__ __forceinline__ void cpasync16(uint32_t s, const void* g) {
    asm volatile("cp.async.cg.shared.global [%0], [%1], 16;\n" :: "r"(s), "l"(g));
}
#define CP_COMMIT() asm volatile("cp.async.commit_group;\n" ::: "memory")
#define CP_WAIT(n)  asm volatile("cp.async.wait_group %0;\n" :: "n"(n) : "memory")
__device__ __forceinline__ unsigned f2tf32(float x) {
    unsigned u; asm("cvt.rna.tf32.f32 %0, %1;" : "=r"(u) : "f"(x)); return u;
}

// ---------------- init: flat per-j tap lists (warp prefix-scan) ----------------
__global__ void k_init() {
    int j = blockIdx.x;
    int k = threadIdx.x;   // 32 threads, one per sample bin
    int h = 0, jj = j;
    while (jj >= DD - h) { jj -= DD - h; h++; }
    int w = h + jj;
    if (k == 0) g_vp[j] = h * DD + w;

    double L = 4.0 * (double)(w - h + 1) + 1.0;
    double sp = 4.0 * (double)h;
    double ep = 4.0 * (double)(w + 1);
    double start_p = sp - 0.5 * L;
    double length  = (ep + 0.5 * L) - start_p;
    double step    = length / 95.0;   // NS*NSPB - 1

    int    tl[6];
    double wl[6];
    int cnt = 0;
    for (int s = 0; s < 3; s++) {
        double pos = start_p + step * (double)(3 * k + s);
        double ip;
        double fr = modf(pos, &ip);
        int it = (int)ip;
        if (it >= 0 && it < TT - 1) {
            int    ta = it,     tb = it + 1;
            double wa = (1.0 - fr) / 3.0, wb2 = fr / 3.0;
            bool fa = false, fb = false;
            for (int e = 0; e < cnt; e++) {
                if (tl[e] == ta) { wl[e] += wa;  fa = true; }
                if (tl[e] == tb) { wl[e] += wb2; fb = true; }
            }
            if (!fa) { tl[cnt] = ta; wl[cnt] = wa;  cnt++; }
            if (!fb) { tl[cnt] = tb; wl[cnt] = wb2; cnt++; }
        }
    }
    // exclusive prefix scan of cnt across the 32 k-threads
    unsigned msk = 0xffffffffu;
    int scan = cnt;
#pragma unroll
    for (int off = 1; off < 32; off <<= 1) {
        int n = __shfl_up_sync(msk, scan, off);
        if (k >= off) scan += n;
    }
    int base = scan - cnt;
    if (k == 31) g_tot[j] = scan;
    for (int e = 0; e < cnt; e++) {
        g_to[j * 192 + base + e] = k * (BB * TT * C3D) + tl[e] * C3D;
        g_wl[j * 192 + base + e] = (float)wl[e];
    }
}

// ---------------- conv1d(k=3,pad=1)+relu -> g_xh[b][t][c] fp16 ------------
__global__ __launch_bounds__(256) void k_conv(const float* __restrict__ base,
                                              const float* __restrict__ w1,
                                              const float* __restrict__ b1) {
    int bid = blockIdx.x;
    int cg = bid & 31, b = bid >> 5;
    int t = threadIdx.x;
    __shared__ float sw[4 * C1D * 3];    // 12 KB
    for (int i = t; i < 4 * C1D * 3; i += 256) sw[i] = w1[cg * 4 * C1D * 3 + i];
    __syncthreads();
    const float* xb = base + (size_t)b * C1D * TT;
    float a0 = b1[cg * 4 + 0], a1 = b1[cg * 4 + 1];
    float a2 = b1[cg * 4 + 2], a3 = b1[cg * 4 + 3];
    for (int ci = 0; ci < C1D; ci++) {
        const float* row = xb + ci * TT;
        float x0 = (t > 0)      ? row[t - 1] : 0.f;
        float x1 = row[t];
        float x2 = (t < TT - 1) ? row[t + 1] : 0.f;
        const float* w = sw + ci * 3;
        a0 += w[0]    * x0 + w[1]    * x1 + w[2]    * x2;
        a1 += w[768]  * x0 + w[769]  * x1 + w[770]  * x2;
        a2 += w[1536] * x0 + w[1537] * x1 + w[1538] * x2;
        a3 += w[2304] * x0 + w[2305] * x1 + w[2306] * x2;
    }
    __half2 h01 = __floats2half2_rn(fmaxf(a0, 0.f), fmaxf(a1, 0.f));
    __half2 h23 = __floats2half2_rn(fmaxf(a2, 0.f), fmaxf(a3, 0.f));
    uint2 pk;
    pk.x = *(uint32_t*)&h01; pk.y = *(uint32_t*)&h23;
    *(uint2*)&g_xh[((size_t)b * TT + t) * C2D + cg * 4] = pk;
}

// ---------------- w3[o][c][k] fp32 -> g_w3p[k][o][c] fp16 ----------------
__global__ void k_tw3p(const float* __restrict__ w3) {
    int o = blockIdx.x, c = threadIdx.x;   // 512 x 128
    const float* src = w3 + ((size_t)o * C2D + c) * NS;
    for (int k = 0; k < NS; k++)
        g_w3p[((size_t)k * C3D + o) * C2D + c] = __float2half_rn(src[k]);
}

// ---------------- z GEMM (f16 mma.sync m16n8k16) ----------------
// z[k][b][t][o] = sum_c x[t][c] * w3p[k][o][c]; fp32 accum, half store.
// CTA 128t x 128o, K=128 in 4 chunks of 32, all 4 staged in smem (80 KB).
#define K2SMEM (4 * 10240 * 2)
__global__ __launch_bounds__(256) void k2_f16() {
    extern __shared__ __align__(16) __half s2[];   // 4 x (A 5120 + B 5120)
    int bid = blockIdx.x;                 // 2048
    int tile = bid & 7, kb = bid >> 3;
    int b = kb & 7, k = kb >> 3;
    int T0 = (tile >> 2) * 128, O0 = (tile & 3) * 128;
    int tid = threadIdx.x;
    int lane = tid & 31, wid = tid >> 5;
    int wt = wid >> 2, wo = wid & 3;      // 2 x 4 warps, warp tile 64 x 32
    int gid = lane >> 2, qid = lane & 3;
    uint32_t sb = smem_u32(s2);

    const __half* Ag = g_xh + ((size_t)(b * TT + T0)) * C2D;
    const __half* Bg = g_w3p + ((size_t)(k * C3D + O0)) * C2D;

#pragma unroll
    for (int it = 0; it < 4; it++) {      // stage all 4 K-chunks
        int c0 = it * 32;
        uint32_t abuf = sb + it * 20480;
        uint32_t bbuf = abuf + 10240;
#pragma unroll
        for (int q = 0; q < 2; q++) {
            int idx = q * 256 + tid;
            int r = idx >> 2, c8 = (idx & 3) * 8;
            uint32_t soff = (uint32_t)(r * 40 + c8) * 2;
            cpasync16(abuf + soff, Ag + (size_t)r * C2D + c0 + c8);
            cpasync16(bbuf + soff, Bg + (size_t)r * C2D + c0 + c8);
        }
        CP_COMMIT();
    }

    float acc[4][4][4];
#pragma unroll
    for (int mi = 0; mi < 4; mi++)
#pragma unroll
        for (int ni = 0; ni < 4; ni++)
#pragma unroll
            for (int r = 0; r < 4; r++) acc[mi][ni][r] = 0.f;

#pragma unroll
    for (int i = 0; i < 4; i++) {
        if (i == 0) { CP_WAIT(3); }
        else if (i == 1) { CP_WAIT(2); }
        else if (i == 2) { CP_WAIT(1); }
        else { CP_WAIT(0); }
        __syncthreads();
        const __half* Ap = s2 + i * 10240;
        const __half* Bp = Ap + 5120;
#pragma unroll
        for (int ks = 0; ks < 2; ks++) {
            int kof = ks * 16 + 2 * qid;
            unsigned Af[4][4], Bf[4][2];
#pragma unroll
            for (int mi = 0; mi < 4; mi++) {
                const __half* ar = Ap + (wt * 64 + mi * 16 + gid) * 40 + kof;
                Af[mi][0] = *(const unsigned*)(ar);
                Af[mi][1] = *(const unsigned*)(ar + 8 * 40);
                Af[mi][2] = *(const unsigned*)(ar + 8);
                Af[mi][3] = *(const unsigned*)(ar + 8 * 40 + 8);
            }
#pragma unroll
            for (int ni = 0; ni < 4; ni++) {
                const __half* br = Bp + (wo * 32 + ni * 8 + gid) * 40 + kof;
                Bf[ni][0] = *(const unsigned*)(br);
                Bf[ni][1] = *(const unsigned*)(br + 8);
            }
#pragma unroll
            for (int mi = 0; mi < 4; mi++)
#pragma unroll
                for (int ni = 0; ni < 4; ni++)
                    asm volatile(
                        "mma.sync.aligned.m16n8k16.row.col.f32.f16.f16.f32 "
                        "{%0,%1,%2,%3}, {%4,%5,%6,%7}, {%8,%9}, {%0,%1,%2,%3};"
                        : "+f"(acc[mi][ni][0]), "+f"(acc[mi][ni][1]),
                          "+f"(acc[mi][ni][2]), "+f"(acc[mi][ni][3])
                        : "r"(Af[mi][0]), "r"(Af[mi][1]), "r"(Af[mi][2]), "r"(Af[mi][3]),
                          "r"(Bf[ni][0]), "r"(Bf[ni][1]));
        }
    }

    size_t zbase = ((size_t)(k * BB + b)) * TT * C3D;
#pragma unroll
    for (int mi = 0; mi < 4; mi++) {
#pragma unroll
        for (int ni = 0; ni < 4; ni++) {
            int t = T0 + wt * 64 + mi * 16 + gid;
            int o = O0 + wo * 32 + ni * 8 + 2 * qid;
            __half2 h0 = __floats2half2_rn(acc[mi][ni][0], acc[mi][ni][1]);
            __half2 h1 = __floats2half2_rn(acc[mi][ni][2], acc[mi][ni][3]);
            *(__half2*)&g_z[zbase + (size_t)t * C3D + o] = h0;
            *(__half2*)&g_z[zbase + (size_t)(t + 8) * C3D + o] = h1;
        }
    }
}

// ---------------- sparse boundary-matching gather (flat uniform list) -------
// x3[b][j][o] = relu(b3[o] + sum_e w_e * z[off_e + b][o])
// One block per j; 512 threads: thread = (b = tid>>6, o = (tid&63)*8 ..+7).
// bid->j remap: same-SM blocks (same bid%148, classic-LUT placement) get
// ADJACENT j, whose tap sets overlap -> z rows hit in per-SM L1 (persists
// within launch) instead of LTS. Pure index permutation, loop unchanged.
__global__ __launch_bounds__(512) void k3_sparse(const float* __restrict__ b3) {
    int bid = blockIdx.x;            // 2080
    int j = (bid < 2072) ? (bid % 148) * 14 + (bid / 148) : bid;
    int tid = threadIdx.x;           // 512
    __shared__ int   sto[192];
    __shared__ float swt[192];
    __shared__ int   stot;
    if (tid < 192) {
        sto[tid] = g_to[j * 192 + tid];
        swt[tid] = g_wl[j * 192 + tid];
    }
    if (tid == 192 + 64) stot = g_tot[j];
    __syncthreads();
    int tot = stot;

    int b = tid >> 6;          // 0..7
    int o0 = (tid & 63) * 8;   // 0..504
    float acc[8] = {0.f,0.f,0.f,0.f,0.f,0.f,0.f,0.f};

    const __half* zb = g_z + (size_t)b * TT * C3D + o0;
#pragma unroll 4
    for (int e = 0; e < tot; e++) {
        int off = sto[e];
        float wgt = swt[e];
        uint4 u = *(const uint4*)(zb + off);
        float2 f0 = __half22float2(*(__half2*)&u.x);
        float2 f1 = __half22float2(*((__half2*)&u.x + 1));
        float2 f2 = __half22float2(*(__half2*)&u.z);
        float2 f3 = __half22float2(*((__half2*)&u.z + 1));
        acc[0] += wgt * f0.x; acc[1] += wgt * f0.y;
        acc[2] += wgt * f1.x; acc[3] += wgt * f1.y;
        acc[4] += wgt * f2.x; acc[5] += wgt * f2.y;
        acc[6] += wgt * f3.x; acc[7] += wgt * f3.y;
    }
    float4 ba  = *(const float4*)&b3[o0];
    float4 bb4 = *(const float4*)&b3[o0 + 4];
    float4 r0, r1;
    r0.x = fmaxf(acc[0] + ba.x, 0.f);  r0.y = fmaxf(acc[1] + ba.y, 0.f);
    r0.z = fmaxf(acc[2] + ba.z, 0.f);  r0.w = fmaxf(acc[3] + ba.w, 0.f);
    r1.x = fmaxf(acc[4] + bb4.x, 0.f); r1.y = fmaxf(acc[5] + bb4.y, 0.f);
    r1.z = fmaxf(acc[6] + bb4.z, 0.f); r1.w = fmaxf(acc[7] + bb4.w, 0.f);
    size_t row = ((size_t)b * NVALID + j) * C3D + o0;
    *(float4*)&g_x3[row]     = r0;
    *(float4*)&g_x3[row + 4] = r1;
}

// ---------------- constant column for h>w pixels ----------------
__global__ void k_const(const float* __restrict__ w2, const float* __restrict__ b2,
                        const float* __restrict__ b3) {
    int m = blockIdx.x, tid = threadIdx.x;
    float s = 0.f;
    for (int o = tid; o < C3D; o += 128) s += w2[m * C3D + o] * fmaxf(b3[o], 0.f);
#pragma unroll
    for (int off = 16; off; off >>= 1) s += __shfl_down_sync(0xffffffffu, s, off);
    __shared__ float r[4];
    if ((tid & 31) == 0) r[tid >> 5] = s;
    __syncthreads();
    if (tid == 0) g_cst[m] = fmaxf(r[0] + r[1] + r[2] + r[3] + b2[m], 0.f);
}

__global__ void k_fill(float* __restrict__ out) {
    int idx = blockIdx.x * 1024 + threadIdx.x;   // 8*128*4096 total
    int m = (idx >> 12) & 127;
    out[idx] = g_cst[m];
}

// ---------------- final 1x1 conv: tf32 mma.sync ----------------
__global__ __launch_bounds__(256) void k4_tf32(const float* __restrict__ w2,
                                               const float* __restrict__ b2,
                                               float* __restrict__ out) {
    int jt = blockIdx.x, b = blockIdx.y;
    int tid = threadIdx.x;
    int lane = tid & 31, wid = tid >> 5;
    int wt = wid >> 2, wo = wid & 3;
    int gid = lane >> 2, qid = lane & 3;
    __shared__ unsigned sa[32][132];   // [oc][m]
    __shared__ unsigned sbx[32][132];  // [oc][j]
    __shared__ int svp[128];
    int j0 = jt * 128;
    if (tid < 128) svp[tid] = (j0 + tid) < NVALID ? g_vp[j0 + tid] : -1;

    float acc[4][4][4];
#pragma unroll
    for (int mi = 0; mi < 4; mi++)
#pragma unroll
        for (int ni = 0; ni < 4; ni++)
#pragma unroll
            for (int r = 0; r < 4; r++) acc[mi][ni][r] = 0.f;

    for (int o0 = 0; o0 < C3D; o0 += 32) {
#pragma unroll
        for (int s = 0; s < 4; s++) {
            int idx = tid + 256 * s;
            int m = idx >> 3, c4 = (idx & 7) * 4;
            float4 v = *(const float4*)&w2[m * C3D + o0 + c4];
            sa[c4 + 0][m] = f2tf32(v.x); sa[c4 + 1][m] = f2tf32(v.y);
            sa[c4 + 2][m] = f2tf32(v.z); sa[c4 + 3][m] = f2tf32(v.w);
        }
#pragma unroll
        for (int s = 0; s < 4; s++) {
            int idx = tid + 256 * s;
            int jj = idx >> 3, c4 = (idx & 7) * 4;
            float4 v = make_float4(0.f, 0.f, 0.f, 0.f);
            if (j0 + jj < NVALID)
                v = *(const float4*)&g_x3[((size_t)b * NVALID + j0 + jj) * C3D + o0 + c4];
            sbx[c4 + 0][jj] = f2tf32(v.x); sbx[c4 + 1][jj] = f2tf32(v.y);
            sbx[c4 + 2][jj] = f2tf32(v.z); sbx[c4 + 3][jj] = f2tf32(v.w);
        }
        __syncthreads();
#pragma unroll
        for (int ks = 0; ks < 4; ks++) {
            int cof = ks * 8;
            unsigned A[4][4], Bf[4][2];
#pragma unroll
            for (int mi = 0; mi < 4; mi++) {
                int tr = wt * 64 + mi * 16 + gid;
                A[mi][0] = sa[cof + qid][tr];
                A[mi][1] = sa[cof + qid][tr + 8];
                A[mi][2] = sa[cof + 4 + qid][tr];
                A[mi][3] = sa[cof + 4 + qid][tr + 8];
            }
#pragma unroll
            for (int ni = 0; ni < 4; ni++) {
                int ob = wo * 32 + ni * 8 + gid;
                Bf[ni][0] = sbx[cof + qid][ob];
                Bf[ni][1] = sbx[cof + 4 + qid][ob];
            }
#pragma unroll
            for (int mi = 0; mi < 4; mi++)
#pragma unroll
                for (int ni = 0; ni < 4; ni++)
                    asm volatile(
                        "mma.sync.aligned.m16n8k8.row.col.f32.tf32.tf32.f32 "
                        "{%0,%1,%2,%3}, {%4,%5,%6,%7}, {%8,%9}, {%0,%1,%2,%3};"
                        : "+f"(acc[mi][ni][0]), "+f"(acc[mi][ni][1]),
                          "+f"(acc[mi][ni][2]), "+f"(acc[mi][ni][3])
                        : "r"(A[mi][0]), "r"(A[mi][1]), "r"(A[mi][2]), "r"(A[mi][3]),
                          "r"(Bf[ni][0]), "r"(Bf[ni][1]));
        }
        __syncthreads();
    }
#pragma unroll
    for (int mi = 0; mi < 4; mi++) {
        int m = wt * 64 + mi * 16 + gid;
        float bm = __ldg(&b2[m]), bm8 = __ldg(&b2[m + 8]);
        size_t rm  = (size_t)(b * C2D + m) * 4096;
        size_t rm8 = (size_t)(b * C2D + m + 8) * 4096;
#pragma unroll
        for (int ni = 0; ni < 4; ni++) {
            int jj = wo * 32 + ni * 8 + 2 * qid;
            int p0 = svp[jj], p1 = svp[jj + 1];
            if (p0 >= 0) {
                out[rm  + p0] = fmaxf(acc[mi][ni][0] + bm, 0.f);
                out[rm8 + p0] = fmaxf(acc[mi][ni][2] + bm8, 0.f);
            }
            if (p1 >= 0) {
                out[rm  + p1] = fmaxf(acc[mi][ni][1] + bm, 0.f);
                out[rm8 + p1] = fmaxf(acc[mi][ni][3] + bm8, 0.f);
            }
        }
    }
}

// ---------------- launch ----------------
extern "C" void kernel_launch(void* const* d_in, const int* in_sizes, int n_in,
                              void* d_out, int out_size) {
    const float* base = (const float*)d_in[0];
    const float* w1   = (const float*)d_in[1];
    const float* b1   = (const float*)d_in[2];
    const float* w3   = (const float*)d_in[3];
    const float* b3   = (const float*)d_in[4];
    const float* w2   = (const float*)d_in[5];
    const float* b2   = (const float*)d_in[6];
    float* out = (float*)d_out;

    cudaFuncSetAttribute(k2_f16, cudaFuncAttributeMaxDynamicSharedMemorySize, K2SMEM);

    k_init<<<NVALID, NS>>>();                              // 1
    k_conv<<<256, 256>>>(base, w1, b1);                    // 2
    k_tw3p<<<C3D, 128>>>(w3);                              // 3
    k2_f16<<<2048, 256, K2SMEM>>>();                       // 4
    k_const<<<C2D, 128>>>(w2, b2, b3);                     // 5
    k3_sparse<<<NVALID, 512>>>(b3);                        // 6  <- ncu target
    k_fill<<<(BB * C2D * 4096) / 1024, 1024>>>(out);       // 7
    k4_tf32<<<dim3(17, BB), 256>>>(w2, b2, out);           // 8
}

// round 17
// speedup vs baseline: 1.4967x; 1.4967x over previous
#include <cuda_runtime.h>
#include <cuda_fp16.h>
#include <math.h>
#include <stdint.h>

#define BB 8
#define C1D 256
#define C2D 128
#define C3D 512
#define NS 32
#define TT 256
#define DD 64
#define NVALID 2080   // number of (h,w) with h<=w, h,w in [0,64)

// ---------------- device scratch ----------------
__device__ __align__(16) __half g_xh[BB*TT*C2D];          // conv out [b][t][c] 0.5 MB
__device__ __align__(16) __half g_w3p[NS*C3D*C2D];        // w3 [k][o][c] fp16   4 MB
__device__ __align__(16) __half g_z[(size_t)NS*BB*TT*C3D];// z  [k][b][t][o]    67 MB
__device__ float  g_x3[(size_t)BB*NVALID*C3D];            // x3 [b][j][o]       34 MB
__device__ int    g_to[NVALID*192];                       // flat fused z offsets (b=0)
__device__ float  g_wl[NVALID*192];                       // flat tap weights
__device__ int    g_tot[NVALID];                          // taps per j
__device__ int    g_vp[NVALID];
__device__ float  g_cst[C2D];

// ---------------- helpers ----------------
__device__ __forceinline__ uint32_t smem_u32(const void* p) {
    uint32_t a;
    asm("{ .reg .u64 t; cvta.to.shared.u64 t, %1; cvt.u32.u64 %0, t; }" : "=r"(a) : "l"(p));
    return a;
}
__device__ __forceinline__ void cpasync16(uint32_t s, const void* g) {
    asm volatile("cp.async.cg.shared.global [%0], [%1], 16;\n" :: "r"(s), "l"(g));
}
#define CP_COMMIT() asm volatile("cp.async.commit_group;\n" ::: "memory")
#define CP_WAIT(n)  asm volatile("cp.async.wait_group %0;\n" :: "n"(n) : "memory")
__device__ __forceinline__ unsigned f2tf32(float x) {
    unsigned u; asm("cvt.rna.tf32.f32 %0, %1;" : "=r"(u) : "f"(x)); return u;
}

// ---------------- init: flat per-j tap lists (warp prefix-scan) ----------------
__global__ void k_init() {
    int j = blockIdx.x;
    int k = threadIdx.x;   // 32 threads, one per sample bin
    int h = 0, jj = j;
    while (jj >= DD - h) { jj -= DD - h; h++; }
    int w = h + jj;
    if (k == 0) g_vp[j] = h * DD + w;

    double L = 4.0 * (double)(w - h + 1) + 1.0;
    double sp = 4.0 * (double)h;
    double ep = 4.0 * (double)(w + 1);
    double start_p = sp - 0.5 * L;
    double length  = (ep + 0.5 * L) - start_p;
    double step    = length / 95.0;   // NS*NSPB - 1

    int    tl[6];
    double wl[6];
    int cnt = 0;
    for (int s = 0; s < 3; s++) {
        double pos = start_p + step * (double)(3 * k + s);
        double ip;
        double fr = modf(pos, &ip);
        int it = (int)ip;
        if (it >= 0 && it < TT - 1) {
            int    ta = it,     tb = it + 1;
            double wa = (1.0 - fr) / 3.0, wb2 = fr / 3.0;
            bool fa = false, fb = false;
            for (int e = 0; e < cnt; e++) {
                if (tl[e] == ta) { wl[e] += wa;  fa = true; }
                if (tl[e] == tb) { wl[e] += wb2; fb = true; }
            }
            if (!fa) { tl[cnt] = ta; wl[cnt] = wa;  cnt++; }
            if (!fb) { tl[cnt] = tb; wl[cnt] = wb2; cnt++; }
        }
    }
    // exclusive prefix scan of cnt across the 32 k-threads
    unsigned msk = 0xffffffffu;
    int scan = cnt;
#pragma unroll
    for (int off = 1; off < 32; off <<= 1) {
        int n = __shfl_up_sync(msk, scan, off);
        if (k >= off) scan += n;
    }
    int base = scan - cnt;
    if (k == 31) g_tot[j] = scan;
    for (int e = 0; e < cnt; e++) {
        g_to[j * 192 + base + e] = k * (BB * TT * C3D) + tl[e] * C3D;
        g_wl[j * 192 + base + e] = (float)wl[e];
    }
}

// ---------------- conv1d(k=3,pad=1)+relu -> g_xh[b][t][c] fp16 ------------
__global__ __launch_bounds__(256) void k_conv(const float* __restrict__ base,
                                              const float* __restrict__ w1,
                                              const float* __restrict__ b1) {
    int bid = blockIdx.x;
    int cg = bid & 31, b = bid >> 5;
    int t = threadIdx.x;
    __shared__ float sw[4 * C1D * 3];    // 12 KB
    for (int i = t; i < 4 * C1D * 3; i += 256) sw[i] = w1[cg * 4 * C1D * 3 + i];
    __syncthreads();
    const float* xb = base + (size_t)b * C1D * TT;
    float a0 = b1[cg * 4 + 0], a1 = b1[cg * 4 + 1];
    float a2 = b1[cg * 4 + 2], a3 = b1[cg * 4 + 3];
    for (int ci = 0; ci < C1D; ci++) {
        const float* row = xb + ci * TT;
        float x0 = (t > 0)      ? row[t - 1] : 0.f;
        float x1 = row[t];
        float x2 = (t < TT - 1) ? row[t + 1] : 0.f;
        const float* w = sw + ci * 3;
        a0 += w[0]    * x0 + w[1]    * x1 + w[2]    * x2;
        a1 += w[768]  * x0 + w[769]  * x1 + w[770]  * x2;
        a2 += w[1536] * x0 + w[1537] * x1 + w[1538] * x2;
        a3 += w[2304] * x0 + w[2305] * x1 + w[2306] * x2;
    }
    __half2 h01 = __floats2half2_rn(fmaxf(a0, 0.f), fmaxf(a1, 0.f));
    __half2 h23 = __floats2half2_rn(fmaxf(a2, 0.f), fmaxf(a3, 0.f));
    uint2 pk;
    pk.x = *(uint32_t*)&h01; pk.y = *(uint32_t*)&h23;
    *(uint2*)&g_xh[((size_t)b * TT + t) * C2D + cg * 4] = pk;
}

// ---------------- w3[o][c][k] fp32 -> g_w3p[k][o][c] fp16 ----------------
__global__ void k_tw3p(const float* __restrict__ w3) {
    int o = blockIdx.x, c = threadIdx.x;   // 512 x 128
    const float* src = w3 + ((size_t)o * C2D + c) * NS;
    for (int k = 0; k < NS; k++)
        g_w3p[((size_t)k * C3D + o) * C2D + c] = __float2half_rn(src[k]);
}

// ---------------- z GEMM (f16 mma.sync m16n8k16) ----------------
// z[k][b][t][o] = sum_c x[t][c] * w3p[k][o][c]; fp32 accum, half store.
// CTA 128t x 128o, K=128 in 4 chunks of 32. TWO 20KB buffers (40 KB total)
// double-buffered with prefetch distance 2 -> 2 CTAs/SM for latency hiding.
#define K2SMEM (2 * 10240 * 2)
__global__ __launch_bounds__(256) void k2_f16() {
    extern __shared__ __align__(16) __half s2[];   // 2 x (A 5120 + B 5120)
    int bid = blockIdx.x;                 // 2048
    int tile = bid & 7, kb = bid >> 3;
    int b = kb & 7, k = kb >> 3;
    int T0 = (tile >> 2) * 128, O0 = (tile & 3) * 128;
    int tid = threadIdx.x;
    int lane = tid & 31, wid = tid >> 5;
    int wt = wid >> 2, wo = wid & 3;      // 2 x 4 warps, warp tile 64 x 32
    int gid = lane >> 2, qid = lane & 3;
    uint32_t sb = smem_u32(s2);

    const __half* Ag = g_xh + ((size_t)(b * TT + T0)) * C2D;
    const __half* Bg = g_w3p + ((size_t)(k * C3D + O0)) * C2D;

    // stage chunk `it` into buffer it&1
#define K2STAGE(it) do {                                                     \
        int c0 = (it) * 32;                                                  \
        uint32_t abuf = sb + ((it) & 1) * 20480;                             \
        uint32_t bbuf = abuf + 10240;                                        \
        _Pragma("unroll")                                                    \
        for (int q = 0; q < 2; q++) {                                        \
            int idx = q * 256 + tid;                                         \
            int r = idx >> 2, c8 = (idx & 3) * 8;                            \
            uint32_t soff = (uint32_t)(r * 40 + c8) * 2;                     \
            cpasync16(abuf + soff, Ag + (size_t)r * C2D + c0 + c8);          \
            cpasync16(bbuf + soff, Bg + (size_t)r * C2D + c0 + c8);          \
        }                                                                    \
        CP_COMMIT();                                                         \
    } while (0)

    K2STAGE(0);
    K2STAGE(1);

    float acc[4][4][4];
#pragma unroll
    for (int mi = 0; mi < 4; mi++)
#pragma unroll
        for (int ni = 0; ni < 4; ni++)
#pragma unroll
            for (int r = 0; r < 4; r++) acc[mi][ni][r] = 0.f;

#pragma unroll
    for (int i = 0; i < 4; i++) {
        if (i < 3) { CP_WAIT(1); } else { CP_WAIT(0); }
        __syncthreads();                       // chunk i visible to all warps
        const __half* Ap = s2 + (i & 1) * 10240;
        const __half* Bp = Ap + 5120;
#pragma unroll
        for (int ks = 0; ks < 2; ks++) {
            int kof = ks * 16 + 2 * qid;
            unsigned Af[4][4], Bf[4][2];
#pragma unroll
            for (int mi = 0; mi < 4; mi++) {
                const __half* ar = Ap + (wt * 64 + mi * 16 + gid) * 40 + kof;
                Af[mi][0] = *(const unsigned*)(ar);
                Af[mi][1] = *(const unsigned*)(ar + 8 * 40);
                Af[mi][2] = *(const unsigned*)(ar + 8);
                Af[mi][3] = *(const unsigned*)(ar + 8 * 40 + 8);
            }
#pragma unroll
            for (int ni = 0; ni < 4; ni++) {
                const __half* br = Bp + (wo * 32 + ni * 8 + gid) * 40 + kof;
                Bf[ni][0] = *(const unsigned*)(br);
                Bf[ni][1] = *(const unsigned*)(br + 8);
            }
#pragma unroll
            for (int mi = 0; mi < 4; mi++)
#pragma unroll
                for (int ni = 0; ni < 4; ni++)
                    asm volatile(
                        "mma.sync.aligned.m16n8k16.row.col.f32.f16.f16.f32 "
                        "{%0,%1,%2,%3}, {%4,%5,%6,%7}, {%8,%9}, {%0,%1,%2,%3};"
                        : "+f"(acc[mi][ni][0]), "+f"(acc[mi][ni][1]),
                          "+f"(acc[mi][ni][2]), "+f"(acc[mi][ni][3])
                        : "r"(Af[mi][0]), "r"(Af[mi][1]), "r"(Af[mi][2]), "r"(Af[mi][3]),
                          "r"(Bf[ni][0]), "r"(Bf[ni][1]));
        }
        if (i + 2 < 4) {
            __syncthreads();                   // all warps done reading buf i&1
            K2STAGE(i + 2);                    // safe to overwrite it
        }
    }
#undef K2STAGE

    size_t zbase = ((size_t)(k * BB + b)) * TT * C3D;
#pragma unroll
    for (int mi = 0; mi < 4; mi++) {
#pragma unroll
        for (int ni = 0; ni < 4; ni++) {
            int t = T0 + wt * 64 + mi * 16 + gid;
            int o = O0 + wo * 32 + ni * 8 + 2 * qid;
            __half2 h0 = __floats2half2_rn(acc[mi][ni][0], acc[mi][ni][1]);
            __half2 h1 = __floats2half2_rn(acc[mi][ni][2], acc[mi][ni][3]);
            *(__half2*)&g_z[zbase + (size_t)t * C3D + o] = h0;
            *(__half2*)&g_z[zbase + (size_t)(t + 8) * C3D + o] = h1;
        }
    }
}

// ---------------- sparse boundary-matching gather (flat uniform list) -------
// x3[b][j][o] = relu(b3[o] + sum_e w_e * z[off_e + b][o])
// One block per j; 512 threads: thread = (b = tid>>6, o = (tid&63)*8 ..+7).
__global__ __launch_bounds__(512) void k3_sparse(const float* __restrict__ b3) {
    int j = blockIdx.x;              // 2080
    int tid = threadIdx.x;           // 512
    __shared__ int   sto[192];
    __shared__ float swt[192];
    __shared__ int   stot;
    if (tid < 192) {
        sto[tid] = g_to[j * 192 + tid];
        swt[tid] = g_wl[j * 192 + tid];
    }
    if (tid == 192 + 64) stot = g_tot[j];
    __syncthreads();
    int tot = stot;

    int b = tid >> 6;          // 0..7
    int o0 = (tid & 63) * 8;   // 0..504
    float acc[8] = {0.f,0.f,0.f,0.f,0.f,0.f,0.f,0.f};

    const __half* zb = g_z + (size_t)b * TT * C3D + o0;
#pragma unroll 4
    for (int e = 0; e < tot; e++) {
        int off = sto[e];
        float wgt = swt[e];
        uint4 u = *(const uint4*)(zb + off);
        float2 f0 = __half22float2(*(__half2*)&u.x);
        float2 f1 = __half22float2(*((__half2*)&u.x + 1));
        float2 f2 = __half22float2(*(__half2*)&u.z);
        float2 f3 = __half22float2(*((__half2*)&u.z + 1));
        acc[0] += wgt * f0.x; acc[1] += wgt * f0.y;
        acc[2] += wgt * f1.x; acc[3] += wgt * f1.y;
        acc[4] += wgt * f2.x; acc[5] += wgt * f2.y;
        acc[6] += wgt * f3.x; acc[7] += wgt * f3.y;
    }
    float4 ba  = *(const float4*)&b3[o0];
    float4 bb4 = *(const float4*)&b3[o0 + 4];
    float4 r0, r1;
    r0.x = fmaxf(acc[0] + ba.x, 0.f);  r0.y = fmaxf(acc[1] + ba.y, 0.f);
    r0.z = fmaxf(acc[2] + ba.z, 0.f);  r0.w = fmaxf(acc[3] + ba.w, 0.f);
    r1.x = fmaxf(acc[4] + bb4.x, 0.f); r1.y = fmaxf(acc[5] + bb4.y, 0.f);
    r1.z = fmaxf(acc[6] + bb4.z, 0.f); r1.w = fmaxf(acc[7] + bb4.w, 0.f);
    size_t row = ((size_t)b * NVALID + j) * C3D + o0;
    *(float4*)&g_x3[row]     = r0;
    *(float4*)&g_x3[row + 4] = r1;
}

// ---------------- constant column for h>w pixels ----------------
__global__ void k_const(const float* __restrict__ w2, const float* __restrict__ b2,
                        const float* __restrict__ b3) {
    int m = blockIdx.x, tid = threadIdx.x;
    float s = 0.f;
    for (int o = tid; o < C3D; o += 128) s += w2[m * C3D + o] * fmaxf(b3[o], 0.f);
#pragma unroll
    for (int off = 16; off; off >>= 1) s += __shfl_down_sync(0xffffffffu, s, off);
    __shared__ float r[4];
    if ((tid & 31) == 0) r[tid >> 5] = s;
    __syncthreads();
    if (tid == 0) g_cst[m] = fmaxf(r[0] + r[1] + r[2] + r[3] + b2[m], 0.f);
}

__global__ void k_fill(float* __restrict__ out) {
    int idx = blockIdx.x * 1024 + threadIdx.x;   // 8*128*4096 total
    int m = (idx >> 12) & 127;
    out[idx] = g_cst[m];
}

// ---------------- final 1x1 conv: tf32 mma.sync ----------------
__global__ __launch_bounds__(256) void k4_tf32(const float* __restrict__ w2,
                                               const float* __restrict__ b2,
                                               float* __restrict__ out) {
    int jt = blockIdx.x, b = blockIdx.y;
    int tid = threadIdx.x;
    int lane = tid & 31, wid = tid >> 5;
    int wt = wid >> 2, wo = wid & 3;
    int gid = lane >> 2, qid = lane & 3;
    __shared__ unsigned sa[32][132];   // [oc][m]
    __shared__ unsigned sbx[32][132];  // [oc][j]
    __shared__ int svp[128];
    int j0 = jt * 128;
    if (tid < 128) svp[tid] = (j0 + tid) < NVALID ? g_vp[j0 + tid] : -1;

    float acc[4][4][4];
#pragma unroll
    for (int mi = 0; mi < 4; mi++)
#pragma unroll
        for (int ni = 0; ni < 4; ni++)
#pragma unroll
            for (int r = 0; r < 4; r++) acc[mi][ni][r] = 0.f;

    for (int o0 = 0; o0 < C3D; o0 += 32) {
#pragma unroll
        for (int s = 0; s < 4; s++) {
            int idx = tid + 256 * s;
            int m = idx >> 3, c4 = (idx & 7) * 4;
            float4 v = *(const float4*)&w2[m * C3D + o0 + c4];
            sa[c4 + 0][m] = f2tf32(v.x); sa[c4 + 1][m] = f2tf32(v.y);
            sa[c4 + 2][m] = f2tf32(v.z); sa[c4 + 3][m] = f2tf32(v.w);
        }
#pragma unroll
        for (int s = 0; s < 4; s++) {
            int idx = tid + 256 * s;
            int jj = idx >> 3, c4 = (idx & 7) * 4;
            float4 v = make_float4(0.f, 0.f, 0.f, 0.f);
            if (j0 + jj < NVALID)
                v = *(const float4*)&g_x3[((size_t)b * NVALID + j0 + jj) * C3D + o0 + c4];
            sbx[c4 + 0][jj] = f2tf32(v.x); sbx[c4 + 1][jj] = f2tf32(v.y);
            sbx[c4 + 2][jj] = f2tf32(v.z); sbx[c4 + 3][jj] = f2tf32(v.w);
        }
        __syncthreads();
#pragma unroll
        for (int ks = 0; ks < 4; ks++) {
            int cof = ks * 8;
            unsigned A[4][4], Bf[4][2];
#pragma unroll
            for (int mi = 0; mi < 4; mi++) {
                int tr = wt * 64 + mi * 16 + gid;
                A[mi][0] = sa[cof + qid][tr];
                A[mi][1] = sa[cof + qid][tr + 8];
                A[mi][2] = sa[cof + 4 + qid][tr];
                A[mi][3] = sa[cof + 4 + qid][tr + 8];
            }
#pragma unroll
            for (int ni = 0; ni < 4; ni++) {
                int ob = wo * 32 + ni * 8 + gid;
                Bf[ni][0] = sbx[cof + qid][ob];
                Bf[ni][1] = sbx[cof + 4 + qid][ob];
            }
#pragma unroll
            for (int mi = 0; mi < 4; mi++)
#pragma unroll
                for (int ni = 0; ni < 4; ni++)
                    asm volatile(
                        "mma.sync.aligned.m16n8k8.row.col.f32.tf32.tf32.f32 "
                        "{%0,%1,%2,%3}, {%4,%5,%6,%7}, {%8,%9}, {%0,%1,%2,%3};"
                        : "+f"(acc[mi][ni][0]), "+f"(acc[mi][ni][1]),
                          "+f"(acc[mi][ni][2]), "+f"(acc[mi][ni][3])
                        : "r"(A[mi][0]), "r"(A[mi][1]), "r"(A[mi][2]), "r"(A[mi][3]),
                          "r"(Bf[ni][0]), "r"(Bf[ni][1]));
        }
        __syncthreads();
    }
#pragma unroll
    for (int mi = 0; mi < 4; mi++) {
        int m = wt * 64 + mi * 16 + gid;
        float bm = __ldg(&b2[m]), bm8 = __ldg(&b2[m + 8]);
        size_t rm  = (size_t)(b * C2D + m) * 4096;
        size_t rm8 = (size_t)(b * C2D + m + 8) * 4096;
#pragma unroll
        for (int ni = 0; ni < 4; ni++) {
            int jj = wo * 32 + ni * 8 + 2 * qid;
            int p0 = svp[jj], p1 = svp[jj + 1];
            if (p0 >= 0) {
                out[rm  + p0] = fmaxf(acc[mi][ni][0] + bm, 0.f);
                out[rm8 + p0] = fmaxf(acc[mi][ni][2] + bm8, 0.f);
            }
            if (p1 >= 0) {
                out[rm  + p1] = fmaxf(acc[mi][ni][1] + bm, 0.f);
                out[rm8 + p1] = fmaxf(acc[mi][ni][3] + bm8, 0.f);
            }
        }
    }
}

// ---------------- launch ----------------
extern "C" void kernel_launch(void* const* d_in, const int* in_sizes, int n_in,
                              void* d_out, int out_size) {
    const float* base = (const float*)d_in[0];
    const float* w1   = (const float*)d_in[1];
    const float* b1   = (const float*)d_in[2];
    const float* w3   = (const float*)d_in[3];
    const float* b3   = (const float*)d_in[4];
    const float* w2   = (const float*)d_in[5];
    const float* b2   = (const float*)d_in[6];
    float* out = (float*)d_out;

    cudaFuncSetAttribute(k2_f16, cudaFuncAttributeMaxDynamicSharedMemorySize, K2SMEM);

    k_init<<<NVALID, NS>>>();                              // 1
    k_conv<<<256, 256>>>(base, w1, b1);                    // 2
    k_tw3p<<<C3D, 128>>>(w3);                              // 3
    k2_f16<<<2048, 256, K2SMEM>>>();                       // 4
    k_const<<<C2D, 128>>>(w2, b2, b3);                     // 5
    k3_sparse<<<NVALID, 512>>>(b3);                        // 6  <- ncu target
    k_fill<<<(BB * C2D * 4096) / 1024, 1024>>>(out);       // 7
    k4_tf32<<<dim3(17, BB), 256>>>(w2, b2, out);           // 8
}